// round 14
// baseline (speedup 1.0000x reference)
#include <cuda_runtime.h>
#include <cuda_bf16.h>

#define NN 100000
#define NE 3200000
#define DIN 128
#define DH0 64
#define DH1 32
#define NG 1024
#define NC 16

// ---------------- scratch (device globals; 16B-aligned for vector ops) -----
__device__ __align__(16) float g_deg[NN];
__device__ __align__(16) float g_isq[NN];          // deg^-1/2
__device__ __align__(16) int2  g_rc[NE];           // packed (row, col)
__device__ __align__(16) float g_hw0[NN * DH0];    // isq-scaled x @ W0 (message source)
__device__ __align__(16) float g_agg0[NN * DH0];   // seeded with hw0 (self-loop), scatter target
__device__ __align__(16) float g_hw1[NN * DH1];    // isq-scaled h0 @ W1 (message source)
__device__ __align__(16) float g_agg1[NN * DH1];   // seeded with hw1, scatter target

// no-return vector reduction: REDG, never ATOMG
__device__ __forceinline__ void red_add_f32x4(float* p, float4 v) {
    asm volatile("red.global.add.v4.f32 [%0], {%1, %2, %3, %4};"
                 :: "l"(p), "f"(v.x), "f"(v.y), "f"(v.z), "f"(v.w)
                 : "memory");
}

__device__ __forceinline__ int clampi(int v) {
    return min(max(v, 0), NN - 1);
}

// ---------------- prep -------------------------------------------------------
__global__ void k_deg_init() {
    int i = blockIdx.x * blockDim.x + threadIdx.x;
    if (i < NN) g_deg[i] = 1.0f;     // self-loop
}

// INT32 edge indices (JAX canonicalizes int64->int32 without x64).
// 4 edges per thread via int4 loads; indices clamped for crash-free diagnosis.
__global__ void k_edge_prep(const int* __restrict__ ei) {
    int t = blockIdx.x * blockDim.x + threadIdx.x;
    int e = t * 4;
    if (e >= NE) return;
    int4 r4 = *reinterpret_cast<const int4*>(ei + e);        // rows (targets)
    int4 c4 = *reinterpret_cast<const int4*>(ei + NE + e);   // cols (sources)
    int r0 = clampi(r4.x), r1 = clampi(r4.y), r2 = clampi(r4.z), r3 = clampi(r4.w);
    int c0 = clampi(c4.x), c1 = clampi(c4.y), c2 = clampi(c4.z), c3 = clampi(c4.w);
    *reinterpret_cast<int4*>(&g_rc[e])     = make_int4(r0, c0, r1, c1);
    *reinterpret_cast<int4*>(&g_rc[e + 2]) = make_int4(r2, c2, r3, c3);
    atomicAdd(&g_deg[r0], 1.0f);     // no return value -> RED
    atomicAdd(&g_deg[r1], 1.0f);
    atomicAdd(&g_deg[r2], 1.0f);
    atomicAdd(&g_deg[r3], 1.0f);
}

__global__ void k_invsqrt() {
    int i = blockIdx.x * blockDim.x + threadIdx.x;
    if (i < NN) g_isq[i] = rsqrtf(g_deg[i]);
}

// ---------------- GEMM 0: x[N,128] @ W0[128,64], scaled by isq -------------
// writes hw_scaled to BOTH g_hw0 (message source) and g_agg0 (self-loop seed)
// block (16,8) = 128 thr; 32 rows x 64 cols per block; 4x4 register tile.
__global__ void k_gemm0(const float* __restrict__ x, const float* __restrict__ W0) {
    __shared__ float Ws[DIN * DH0];      // 32 KB, [k][64]
    __shared__ float xs[32 * DIN];       // 16 KB, [row][k]
    int tx = threadIdx.x;                // 0..15 -> cols tx*4
    int ty = threadIdx.y;                // 0..7  -> rows ty*4
    int tid = ty * 16 + tx;
    int row0 = blockIdx.x * 32;

    for (int i = tid; i < DIN * DH0 / 4; i += 128)
        reinterpret_cast<float4*>(Ws)[i] = reinterpret_cast<const float4*>(W0)[i];
    for (int i = tid; i < 32 * DIN / 4; i += 128) {
        int r = i >> 5, k4 = i & 31;     // 32 float4 per row
        int gr = row0 + r;
        reinterpret_cast<float4*>(xs)[i] = (gr < NN)
            ? reinterpret_cast<const float4*>(x + gr * DIN)[k4]
            : make_float4(0.f, 0.f, 0.f, 0.f);
    }
    __syncthreads();

    float acc[4][4] = {};
    for (int k = 0; k < DIN; k++) {
        float4 w = *reinterpret_cast<const float4*>(Ws + k * DH0 + tx * 4);
        float a0 = xs[(ty * 4 + 0) * DIN + k];
        float a1 = xs[(ty * 4 + 1) * DIN + k];
        float a2 = xs[(ty * 4 + 2) * DIN + k];
        float a3 = xs[(ty * 4 + 3) * DIN + k];
        acc[0][0] += a0 * w.x; acc[0][1] += a0 * w.y; acc[0][2] += a0 * w.z; acc[0][3] += a0 * w.w;
        acc[1][0] += a1 * w.x; acc[1][1] += a1 * w.y; acc[1][2] += a1 * w.z; acc[1][3] += a1 * w.w;
        acc[2][0] += a2 * w.x; acc[2][1] += a2 * w.y; acc[2][2] += a2 * w.z; acc[2][3] += a2 * w.w;
        acc[3][0] += a3 * w.x; acc[3][1] += a3 * w.y; acc[3][2] += a3 * w.z; acc[3][3] += a3 * w.w;
    }
    #pragma unroll
    for (int j = 0; j < 4; j++) {
        int r = row0 + ty * 4 + j;
        if (r < NN) {
            float s = g_isq[r];          // fold GCN norm into features
            float4 v = make_float4(acc[j][0] * s, acc[j][1] * s, acc[j][2] * s, acc[j][3] * s);
            *reinterpret_cast<float4*>(g_hw0 + r * DH0 + tx * 4) = v;
            *reinterpret_cast<float4*>(g_agg0 + r * DH0 + tx * 4) = v;  // self-loop seed
        }
    }
}

// ---------------- GEMM 1: relu(isq*agg0+b0)[N,64] @ W1[64,32], scaled ------
// fused relu0 in the smem load; block (8,16)=128 thr; 64x32 tile; 4x4 reg tile.
__global__ void k_gemm1(const float* __restrict__ W1, const float* __restrict__ b0) {
    __shared__ float Ws[DH0 * DH1];      // 8 KB, [k][32]
    __shared__ float hs[64 * DH0];       // 16 KB, [row][k]
    int tx = threadIdx.x;                // 0..7  -> cols tx*4
    int ty = threadIdx.y;                // 0..15 -> rows ty*4
    int tid = ty * 8 + tx;
    int row0 = blockIdx.x * 64;

    for (int i = tid; i < DH0 * DH1 / 4; i += 128)
        reinterpret_cast<float4*>(Ws)[i] = reinterpret_cast<const float4*>(W1)[i];
    for (int i = tid; i < 64 * DH0 / 4; i += 128) {
        int r = i >> 4, k4 = i & 15;     // 16 float4 per row
        int gr = row0 + r;
        float4 v = make_float4(0.f, 0.f, 0.f, 0.f);
        if (gr < NN) {
            float is = g_isq[gr];
            float4 a = reinterpret_cast<const float4*>(g_agg0 + gr * DH0)[k4];
            float4 b = reinterpret_cast<const float4*>(b0)[k4];
            v.x = fmaxf(fmaf(a.x, is, b.x), 0.f);   // fused relu0
            v.y = fmaxf(fmaf(a.y, is, b.y), 0.f);
            v.z = fmaxf(fmaf(a.z, is, b.z), 0.f);
            v.w = fmaxf(fmaf(a.w, is, b.w), 0.f);
        }
        reinterpret_cast<float4*>(hs)[i] = v;
    }
    __syncthreads();

    float acc[4][4] = {};
    for (int k = 0; k < DH0; k++) {
        float4 w = *reinterpret_cast<const float4*>(Ws + k * DH1 + tx * 4);
        float a0 = hs[(ty * 4 + 0) * DH0 + k];
        float a1 = hs[(ty * 4 + 1) * DH0 + k];
        float a2 = hs[(ty * 4 + 2) * DH0 + k];
        float a3 = hs[(ty * 4 + 3) * DH0 + k];
        acc[0][0] += a0 * w.x; acc[0][1] += a0 * w.y; acc[0][2] += a0 * w.z; acc[0][3] += a0 * w.w;
        acc[1][0] += a1 * w.x; acc[1][1] += a1 * w.y; acc[1][2] += a1 * w.z; acc[1][3] += a1 * w.w;
        acc[2][0] += a2 * w.x; acc[2][1] += a2 * w.y; acc[2][2] += a2 * w.z; acc[2][3] += a2 * w.w;
        acc[3][0] += a3 * w.x; acc[3][1] += a3 * w.y; acc[3][2] += a3 * w.z; acc[3][3] += a3 * w.w;
    }
    #pragma unroll
    for (int j = 0; j < 4; j++) {
        int r = row0 + ty * 4 + j;
        if (r < NN) {
            float s = g_isq[r];
            float4 v = make_float4(acc[j][0] * s, acc[j][1] * s, acc[j][2] * s, acc[j][3] * s);
            *reinterpret_cast<float4*>(g_hw1 + r * DH1 + tx * 4) = v;
            *reinterpret_cast<float4*>(g_agg1 + r * DH1 + tx * 4) = v;  // self-loop seed
        }
    }
}

// ---------------- edge scatter (REDG float4, unweighted) -------------------
// layer 0: 2 threads per edge; each does 8 gathers + 8 REDs (128 B half-row)
__global__ void k_scatter0() {
    int idx = blockIdx.x * blockDim.x + threadIdx.x;   // NE*2 threads
    if (idx >= NE * 2) return;
    int e = idx >> 1, s = idx & 1;
    int2 rc = g_rc[e];
    const float4* src = reinterpret_cast<const float4*>(g_hw0 + rc.y * DH0) + s;
    float4* dst = reinterpret_cast<float4*>(g_agg0 + rc.x * DH0) + s;
    float4 v0 = src[0],  v1 = src[2],  v2 = src[4],  v3 = src[6];
    float4 v4 = src[8],  v5 = src[10], v6 = src[12], v7 = src[14];
    red_add_f32x4((float*)(dst + 0),  v0);
    red_add_f32x4((float*)(dst + 2),  v1);
    red_add_f32x4((float*)(dst + 4),  v2);
    red_add_f32x4((float*)(dst + 6),  v3);
    red_add_f32x4((float*)(dst + 8),  v4);
    red_add_f32x4((float*)(dst + 10), v5);
    red_add_f32x4((float*)(dst + 12), v6);
    red_add_f32x4((float*)(dst + 14), v7);
}

// layer 1: 1 thread per edge; full 128 B row (8 gathers + 8 REDs)
__global__ void k_scatter1() {
    int e = blockIdx.x * blockDim.x + threadIdx.x;
    if (e >= NE) return;
    int2 rc = g_rc[e];
    const float4* src = reinterpret_cast<const float4*>(g_hw1 + rc.y * DH1);
    float4* dst = reinterpret_cast<float4*>(g_agg1 + rc.x * DH1);
    float4 v0 = src[0], v1 = src[1], v2 = src[2], v3 = src[3];
    float4 v4 = src[4], v5 = src[5], v6 = src[6], v7 = src[7];
    red_add_f32x4((float*)(dst + 0), v0);
    red_add_f32x4((float*)(dst + 1), v1);
    red_add_f32x4((float*)(dst + 2), v2);
    red_add_f32x4((float*)(dst + 3), v3);
    red_add_f32x4((float*)(dst + 4), v4);
    red_add_f32x4((float*)(dst + 5), v5);
    red_add_f32x4((float*)(dst + 6), v6);
    red_add_f32x4((float*)(dst + 7), v7);
}

// ---------------- mean pool (fused relu1) + dense head ---------------------
// 4 warps per graph: strided node partition, smem reduce, lanes 0..15 head.
// node_graph_index is INT32 (JAX canonicalization).
__global__ void k_pool_dense(const int* __restrict__ ngi,
                             const float* __restrict__ b1,
                             const float* __restrict__ Wd,
                             const float* __restrict__ bd,
                             float* __restrict__ out) {
    int g = blockIdx.x;
    int lane = threadIdx.x & 31;
    int w = threadIdx.x >> 5;            // 0..3

    int lo = 0, hi = NN;
    while (lo < hi) { int m = (lo + hi) >> 1; if (ngi[m] < g) lo = m + 1; else hi = m; }
    int start = lo;
    hi = NN;
    while (lo < hi) { int m = (lo + hi) >> 1; if (ngi[m] < g + 1) lo = m + 1; else hi = m; }
    int end = lo;

    float bl = b1[lane];
    float acc = 0.f;
    for (int n = start + w; n < end; n += 4) {
        float is = g_isq[n];
        float a = g_agg1[n * DH1 + lane];
        acc += fmaxf(fmaf(a, is, bl), 0.f);           // fused relu1
    }

    __shared__ float sm[4][DH1];
    sm[w][lane] = acc;
    __syncthreads();

    if (w == 0) {
        float tot = sm[0][lane] + sm[1][lane] + sm[2][lane] + sm[3][lane];
        float cnt = (float)(end - start);
        sm[0][lane] = tot / fmaxf(cnt, 1.0f);
    }
    __syncthreads();

    if (threadIdx.x < NC) {
        float s = bd[threadIdx.x];
        #pragma unroll
        for (int f = 0; f < DH1; f++)
            s += sm[0][f] * Wd[f * NC + threadIdx.x];
        out[g * NC + threadIdx.x] = s;
    }
}

// ---------------- launch ----------------------------------------------------
extern "C" void kernel_launch(void* const* d_in, const int* in_sizes, int n_in,
                              void* d_out, int out_size) {
    const float* x   = (const float*)d_in[0];
    const int*   ei  = (const int*)d_in[1];     // int32 (JAX canonicalizes int64)
    const int*   ngi = (const int*)d_in[2];     // int32
    const float* W0  = (const float*)d_in[3];
    const float* b0  = (const float*)d_in[4];
    const float* W1  = (const float*)d_in[5];
    const float* b1  = (const float*)d_in[6];
    const float* Wd  = (const float*)d_in[7];
    const float* bd  = (const float*)d_in[8];
    float* out = (float*)d_out;

    const int T = 256;
    // degree / isq precompute (must precede gemm0: norm folded into epilogue)
    k_deg_init<<<(NN + T - 1) / T, T>>>();
    k_edge_prep<<<(NE / 4 + T - 1) / T, T>>>(ei);
    k_invsqrt<<<(NN + T - 1) / T, T>>>();

    // layer 0
    k_gemm0<<<(NN + 31) / 32, dim3(16, 8)>>>(x, W0);
    k_scatter0<<<(NE * 2 + T - 1) / T, T>>>();

    // layer 1 (relu0 fused into gemm1 load)
    k_gemm1<<<(NN + 63) / 64, dim3(8, 16)>>>(W1, b0);
    k_scatter1<<<(NE + T - 1) / T, T>>>();

    // pool (relu1 fused) + dense head
    k_pool_dense<<<NG, 128>>>(ngi, b1, Wd, bd, out);
}

// round 17
// speedup vs baseline: 1.2236x; 1.2236x over previous
#include <cuda_runtime.h>
#include <cuda_bf16.h>

#define NN 100000
#define NE 3200000
#define DIN 128
#define DH0 64
#define DH1 32
#define NG 1024
#define NC 16

// ---------------- scratch (device globals; 16B-aligned) --------------------
__device__ __align__(16) int   g_cnt[NN];          // edge count per dest row
__device__ __align__(16) int   g_rowptr[NN + 1];   // CSR row pointers
__device__ __align__(16) int   g_cursor[NN];       // fill cursors (start at rowptr)
__device__ __align__(16) int   g_csr[NE];          // source col per edge, grouped by dest
__device__ __align__(16) float g_isq[NN];          // (1+deg)^-1/2
__device__ __align__(16) float g_hw0[NN * DH0];    // isq-scaled x @ W0
__device__ __align__(16) float g_agg0[NN * DH0];   // gathered sums (incl self)
__device__ __align__(16) float g_hw1[NN * DH1];    // isq-scaled h0 @ W1
__device__ __align__(16) float g_agg1[NN * DH1];   // gathered sums (incl self)

__device__ __forceinline__ int clampi(int v) {
    return min(max(v, 0), NN - 1);
}

// ---------------- CSR build -------------------------------------------------
__global__ void k_cnt_zero() {
    int i = blockIdx.x * blockDim.x + threadIdx.x;
    if (i < NN) g_cnt[i] = 0;
}

// count edges per dest row; 4 edges per thread via int4 loads (int32 indices)
__global__ void k_count(const int* __restrict__ ei) {
    int t = blockIdx.x * blockDim.x + threadIdx.x;
    int e = t * 4;
    if (e >= NE) return;
    int4 r4 = *reinterpret_cast<const int4*>(ei + e);
    atomicAdd(&g_cnt[clampi(r4.x)], 1);
    atomicAdd(&g_cnt[clampi(r4.y)], 1);
    atomicAdd(&g_cnt[clampi(r4.z)], 1);
    atomicAdd(&g_cnt[clampi(r4.w)], 1);
}

// single-block exclusive scan over 100K counts; also fills cursor + isq
__global__ void k_scan() {
    __shared__ int s[1024];
    int t = threadIdx.x;
    const int CH = (NN + 1023) / 1024;         // 98
    int lo = t * CH, hi = min(lo + CH, NN);
    int sum = 0;
    for (int i = lo; i < hi; i++) sum += g_cnt[i];
    s[t] = sum;
    __syncthreads();
    for (int d = 1; d < 1024; d <<= 1) {        // Hillis-Steele inclusive scan
        int v = (t >= d) ? s[t - d] : 0;
        __syncthreads();
        s[t] += v;
        __syncthreads();
    }
    int off = (t == 0) ? 0 : s[t - 1];          // exclusive offset for this chunk
    for (int i = lo; i < hi; i++) {
        int c = g_cnt[i];
        g_rowptr[i] = off;
        g_cursor[i] = off;
        g_isq[i] = rsqrtf((float)(c + 1));      // +1 self-loop
        off += c;
    }
    if (t == 1023) g_rowptr[NN] = off;
}

// fill CSR: 2 edges per thread
__global__ void k_fill(const int* __restrict__ ei) {
    int t = blockIdx.x * blockDim.x + threadIdx.x;
    int e = t * 2;
    if (e >= NE) return;
    int2 r2 = *reinterpret_cast<const int2*>(ei + e);
    int2 c2 = *reinterpret_cast<const int2*>(ei + NE + e);
    int p0 = atomicAdd(&g_cursor[clampi(r2.x)], 1);
    g_csr[p0] = clampi(c2.x);
    int p1 = atomicAdd(&g_cursor[clampi(r2.y)], 1);
    g_csr[p1] = clampi(c2.y);
}

// ---------------- GEMM 0: x[N,128] @ W0[128,64], scaled by isq -------------
// block (16,8) = 128 thr; 32 rows x 64 cols per block; 4x4 register tile.
__global__ void k_gemm0(const float* __restrict__ x, const float* __restrict__ W0) {
    __shared__ float Ws[DIN * DH0];      // 32 KB, [k][64]
    __shared__ float xs[32 * DIN];       // 16 KB, [row][k]
    int tx = threadIdx.x;
    int ty = threadIdx.y;
    int tid = ty * 16 + tx;
    int row0 = blockIdx.x * 32;

    for (int i = tid; i < DIN * DH0 / 4; i += 128)
        reinterpret_cast<float4*>(Ws)[i] = reinterpret_cast<const float4*>(W0)[i];
    for (int i = tid; i < 32 * DIN / 4; i += 128) {
        int r = i >> 5, k4 = i & 31;
        int gr = row0 + r;
        reinterpret_cast<float4*>(xs)[i] = (gr < NN)
            ? reinterpret_cast<const float4*>(x + gr * DIN)[k4]
            : make_float4(0.f, 0.f, 0.f, 0.f);
    }
    __syncthreads();

    float acc[4][4] = {};
    for (int k = 0; k < DIN; k++) {
        float4 w = *reinterpret_cast<const float4*>(Ws + k * DH0 + tx * 4);
        float a0 = xs[(ty * 4 + 0) * DIN + k];
        float a1 = xs[(ty * 4 + 1) * DIN + k];
        float a2 = xs[(ty * 4 + 2) * DIN + k];
        float a3 = xs[(ty * 4 + 3) * DIN + k];
        acc[0][0] += a0 * w.x; acc[0][1] += a0 * w.y; acc[0][2] += a0 * w.z; acc[0][3] += a0 * w.w;
        acc[1][0] += a1 * w.x; acc[1][1] += a1 * w.y; acc[1][2] += a1 * w.z; acc[1][3] += a1 * w.w;
        acc[2][0] += a2 * w.x; acc[2][1] += a2 * w.y; acc[2][2] += a2 * w.z; acc[2][3] += a2 * w.w;
        acc[3][0] += a3 * w.x; acc[3][1] += a3 * w.y; acc[3][2] += a3 * w.z; acc[3][3] += a3 * w.w;
    }
    #pragma unroll
    for (int j = 0; j < 4; j++) {
        int r = row0 + ty * 4 + j;
        if (r < NN) {
            float s = g_isq[r];          // fold GCN norm into features
            *reinterpret_cast<float4*>(g_hw0 + r * DH0 + tx * 4) =
                make_float4(acc[j][0] * s, acc[j][1] * s, acc[j][2] * s, acc[j][3] * s);
        }
    }
}

// ---------------- GEMM 1: relu(isq*agg0+b0)[N,64] @ W1[64,32], scaled ------
__global__ void k_gemm1(const float* __restrict__ W1, const float* __restrict__ b0) {
    __shared__ float Ws[DH0 * DH1];      // 8 KB
    __shared__ float hs[64 * DH0];       // 16 KB
    int tx = threadIdx.x;
    int ty = threadIdx.y;
    int tid = ty * 8 + tx;
    int row0 = blockIdx.x * 64;

    for (int i = tid; i < DH0 * DH1 / 4; i += 128)
        reinterpret_cast<float4*>(Ws)[i] = reinterpret_cast<const float4*>(W1)[i];
    for (int i = tid; i < 64 * DH0 / 4; i += 128) {
        int r = i >> 4, k4 = i & 15;
        int gr = row0 + r;
        float4 v = make_float4(0.f, 0.f, 0.f, 0.f);
        if (gr < NN) {
            float is = g_isq[gr];
            float4 a = reinterpret_cast<const float4*>(g_agg0 + gr * DH0)[k4];
            float4 b = reinterpret_cast<const float4*>(b0)[k4];
            v.x = fmaxf(fmaf(a.x, is, b.x), 0.f);   // fused relu0
            v.y = fmaxf(fmaf(a.y, is, b.y), 0.f);
            v.z = fmaxf(fmaf(a.z, is, b.z), 0.f);
            v.w = fmaxf(fmaf(a.w, is, b.w), 0.f);
        }
        reinterpret_cast<float4*>(hs)[i] = v;
    }
    __syncthreads();

    float acc[4][4] = {};
    for (int k = 0; k < DH0; k++) {
        float4 w = *reinterpret_cast<const float4*>(Ws + k * DH1 + tx * 4);
        float a0 = hs[(ty * 4 + 0) * DH0 + k];
        float a1 = hs[(ty * 4 + 1) * DH0 + k];
        float a2 = hs[(ty * 4 + 2) * DH0 + k];
        float a3 = hs[(ty * 4 + 3) * DH0 + k];
        acc[0][0] += a0 * w.x; acc[0][1] += a0 * w.y; acc[0][2] += a0 * w.z; acc[0][3] += a0 * w.w;
        acc[1][0] += a1 * w.x; acc[1][1] += a1 * w.y; acc[1][2] += a1 * w.z; acc[1][3] += a1 * w.w;
        acc[2][0] += a2 * w.x; acc[2][1] += a2 * w.y; acc[2][2] += a2 * w.z; acc[2][3] += a2 * w.w;
        acc[3][0] += a3 * w.x; acc[3][1] += a3 * w.y; acc[3][2] += a3 * w.z; acc[3][3] += a3 * w.w;
    }
    #pragma unroll
    for (int j = 0; j < 4; j++) {
        int r = row0 + ty * 4 + j;
        if (r < NN) {
            float s = g_isq[r];
            *reinterpret_cast<float4*>(g_hw1 + r * DH1 + tx * 4) =
                make_float4(acc[j][0] * s, acc[j][1] * s, acc[j][2] * s, acc[j][3] * s);
        }
    }
}

// ---------------- CSR gather (no atomics) ----------------------------------
// layer 0: warp per node; lane owns float2 (64 floats / 32 lanes)
__global__ void k_gather0() {
    int node = blockIdx.x * 8 + (threadIdx.x >> 5);
    if (node >= NN) return;
    int lane = threadIdx.x & 31;
    int beg = g_rowptr[node], end = g_rowptr[node + 1];
    const float2* hw = reinterpret_cast<const float2*>(g_hw0);
    float2 acc = hw[node * 32 + lane];              // self-loop seed
    int i = beg;
    for (; i + 4 <= end; i += 4) {
        int c0 = g_csr[i], c1 = g_csr[i + 1], c2 = g_csr[i + 2], c3 = g_csr[i + 3];
        float2 v0 = hw[c0 * 32 + lane];
        float2 v1 = hw[c1 * 32 + lane];
        float2 v2 = hw[c2 * 32 + lane];
        float2 v3 = hw[c3 * 32 + lane];
        acc.x += (v0.x + v1.x) + (v2.x + v3.x);
        acc.y += (v0.y + v1.y) + (v2.y + v3.y);
    }
    for (; i < end; i++) {
        float2 v = hw[g_csr[i] * 32 + lane];
        acc.x += v.x; acc.y += v.y;
    }
    reinterpret_cast<float2*>(g_agg0)[node * 32 + lane] = acc;
}

// layer 1: warp per node; lane owns 1 float (32 floats / 32 lanes)
__global__ void k_gather1() {
    int node = blockIdx.x * 8 + (threadIdx.x >> 5);
    if (node >= NN) return;
    int lane = threadIdx.x & 31;
    int beg = g_rowptr[node], end = g_rowptr[node + 1];
    float acc = g_hw1[node * DH1 + lane];           // self-loop seed
    int i = beg;
    for (; i + 4 <= end; i += 4) {
        int c0 = g_csr[i], c1 = g_csr[i + 1], c2 = g_csr[i + 2], c3 = g_csr[i + 3];
        float v0 = g_hw1[c0 * DH1 + lane];
        float v1 = g_hw1[c1 * DH1 + lane];
        float v2 = g_hw1[c2 * DH1 + lane];
        float v3 = g_hw1[c3 * DH1 + lane];
        acc += (v0 + v1) + (v2 + v3);
    }
    for (; i < end; i++)
        acc += g_hw1[g_csr[i] * DH1 + lane];
    g_agg1[node * DH1 + lane] = acc;
}

// ---------------- mean pool (fused relu1) + dense head ---------------------
__global__ void k_pool_dense(const int* __restrict__ ngi,
                             const float* __restrict__ b1,
                             const float* __restrict__ Wd,
                             const float* __restrict__ bd,
                             float* __restrict__ out) {
    int g = blockIdx.x;
    int lane = threadIdx.x & 31;
    int w = threadIdx.x >> 5;            // 0..3

    int lo = 0, hi = NN;
    while (lo < hi) { int m = (lo + hi) >> 1; if (ngi[m] < g) lo = m + 1; else hi = m; }
    int start = lo;
    hi = NN;
    while (lo < hi) { int m = (lo + hi) >> 1; if (ngi[m] < g + 1) lo = m + 1; else hi = m; }
    int end = lo;

    float bl = b1[lane];
    float acc = 0.f;
    for (int n = start + w; n < end; n += 4) {
        float is = g_isq[n];
        float a = g_agg1[n * DH1 + lane];
        acc += fmaxf(fmaf(a, is, bl), 0.f);           // fused relu1
    }

    __shared__ float sm[4][DH1];
    sm[w][lane] = acc;
    __syncthreads();

    if (w == 0) {
        float tot = sm[0][lane] + sm[1][lane] + sm[2][lane] + sm[3][lane];
        float cnt = (float)(end - start);
        sm[0][lane] = tot / fmaxf(cnt, 1.0f);
    }
    __syncthreads();

    if (threadIdx.x < NC) {
        float s = bd[threadIdx.x];
        #pragma unroll
        for (int f = 0; f < DH1; f++)
            s += sm[0][f] * Wd[f * NC + threadIdx.x];
        out[g * NC + threadIdx.x] = s;
    }
}

// ---------------- launch ----------------------------------------------------
extern "C" void kernel_launch(void* const* d_in, const int* in_sizes, int n_in,
                              void* d_out, int out_size) {
    const float* x   = (const float*)d_in[0];
    const int*   ei  = (const int*)d_in[1];     // int32 (JAX canonicalization)
    const int*   ngi = (const int*)d_in[2];     // int32
    const float* W0  = (const float*)d_in[3];
    const float* b0  = (const float*)d_in[4];
    const float* W1  = (const float*)d_in[5];
    const float* b1  = (const float*)d_in[6];
    const float* Wd  = (const float*)d_in[7];
    const float* bd  = (const float*)d_in[8];
    float* out = (float*)d_out;

    const int T = 256;
    // CSR build: count -> scan (also isq) -> fill
    k_cnt_zero<<<(NN + T - 1) / T, T>>>();
    k_count<<<(NE / 4 + T - 1) / T, T>>>(ei);
    k_scan<<<1, 1024>>>();
    k_fill<<<(NE / 2 + T - 1) / T, T>>>(ei);

    // layer 0
    k_gemm0<<<(NN + 31) / 32, dim3(16, 8)>>>(x, W0);
    k_gather0<<<(NN + 7) / 8, T>>>();

    // layer 1 (relu0 fused into gemm1 load)
    k_gemm1<<<(NN + 63) / 64, dim3(8, 16)>>>(W1, b0);
    k_gather1<<<(NN + 7) / 8, T>>>();

    // pool (relu1 fused) + dense head
    k_pool_dense<<<NG, 128>>>(ngi, b1, Wd, bd, out);
}